// round 12
// baseline (speedup 1.0000x reference)
#include <cuda_runtime.h>
#include <cuda_bf16.h>

#define N_NODES  50000
#define D_IN     128
#define D_HID    16
#define E_MAX    800000
#define CAP      128            // bucket capacity per node (Poisson(16): overflow prob ~0)
#define CAP_SHIFT 7

// ---- scratch (__device__ globals; zero-initialized at load; self-cleaning) ----
__device__ int g_cnt[N_NODES];                    // degree; reset by k_gather2out
__device__ int g_eidx[N_NODES * CAP];             // src buckets, one fixed region per dst
__device__ int g_done;                            // fill-blocks-finished counter; reset by k_gather2out
__device__ __align__(16) float g_h1s[N_NODES * D_HID];  // (x@W1) * dinv_i
__device__ __align__(16) float g_zs [N_NODES * D_HID];  // z * dinv_i

__device__ __forceinline__ float4 ldcg4(const float* p) {
    float4 v;
    asm volatile("ld.global.cg.v4.f32 {%0,%1,%2,%3}, [%4];"
                 : "=f"(v.x), "=f"(v.y), "=f"(v.z), "=f"(v.w) : "l"(p));
    return v;
}
__device__ __forceinline__ int ldcg1(const int* p) {
    int v;
    asm volatile("ld.global.cg.s32 %0, [%1];" : "=r"(v) : "l"(p));
    return v;
}
__device__ __forceinline__ int ld_acquire(const int* p) {
    int v;
    asm volatile("ld.acquire.gpu.b32 %0, [%1];" : "=r"(v) : "l"(p) : "memory");
    return v;
}

// ---- packed f32x2 (Blackwell FFMA2; ptxas never auto-emits) ----
__device__ __forceinline__ unsigned long long pack2(float lo, float hi) {
    unsigned long long r;
    asm("mov.b64 %0, {%1, %2};" : "=l"(r) : "f"(lo), "f"(hi));
    return r;
}
__device__ __forceinline__ void unpack2(unsigned long long p, float& lo, float& hi) {
    asm("mov.b64 {%0, %1}, %2;" : "=f"(lo), "=f"(hi) : "l"(p));
}
__device__ __forceinline__ void fma2(unsigned long long& acc, unsigned long long a,
                                     unsigned long long b) {
    asm("fma.rn.f32x2 %0, %1, %2, %0;" : "+l"(acc) : "l"(a), "l"(b));
}
__device__ __forceinline__ void lds_v2u64(unsigned addr, unsigned long long& w01,
                                          unsigned long long& w23) {
    asm("ld.shared.v2.u64 {%0, %1}, [%2];" : "=l"(w01), "=l"(w23) : "r"(addr));
}
__device__ __forceinline__ void ldg_v2u64(const float* p, unsigned long long& w01,
                                          unsigned long long& w23) {
    asm("ld.global.nc.v2.u64 {%0, %1}, [%2];" : "=l"(w01), "=l"(w23) : "l"(p));
}

#define G1_TILE 64
#define G1_XPAD 132
#define FILL_BLOCKS ((E_MAX / 16 + 255) / 256)    // 196 for E=800000

// ---------------------------------------------------------------------------
// Fat kernel: blocks [0,FILL_BLOCKS) build CSR buckets; remaining blocks
// compute h1 = x @ W1 in registers (overlapped), then spin on the fill-done
// counter, and finally scale by dinv and store. No separate k_scale pass.
__global__ void k_fill_gemm1(const int* __restrict__ src, const int* __restrict__ dst,
                             int E, const float* __restrict__ x,
                             const float* __restrict__ W1) {
    __shared__ __align__(16) float sW[D_IN * D_HID];       // 8 KB
    __shared__ __align__(16) float sX[G1_TILE * G1_XPAD];  // ~33 KB

    if (blockIdx.x < FILL_BLOCKS) {
        // ---------------- fill: 16 edges per thread ----------------
        int t = blockIdx.x * blockDim.x + threadIdx.x;
        int e0 = t * 16;
        if (e0 + 15 < E) {
            int4 d[4], s[4];
#pragma unroll
            for (int c = 0; c < 4; c++) {
                d[c] = *(const int4*)(dst + e0 + c * 4);
                s[c] = *(const int4*)(src + e0 + c * 4);
            }
            int p[16];
#pragma unroll
            for (int c = 0; c < 4; c++) {
                p[c * 4 + 0] = atomicAdd(&g_cnt[d[c].x], 1);
                p[c * 4 + 1] = atomicAdd(&g_cnt[d[c].y], 1);
                p[c * 4 + 2] = atomicAdd(&g_cnt[d[c].z], 1);
                p[c * 4 + 3] = atomicAdd(&g_cnt[d[c].w], 1);
            }
#pragma unroll
            for (int c = 0; c < 4; c++) {
                if (p[c*4+0] < CAP) g_eidx[(d[c].x << CAP_SHIFT) + p[c*4+0]] = s[c].x;
                if (p[c*4+1] < CAP) g_eidx[(d[c].y << CAP_SHIFT) + p[c*4+1]] = s[c].y;
                if (p[c*4+2] < CAP) g_eidx[(d[c].z << CAP_SHIFT) + p[c*4+2]] = s[c].z;
                if (p[c*4+3] < CAP) g_eidx[(d[c].w << CAP_SHIFT) + p[c*4+3]] = s[c].w;
            }
        } else {
            for (int e = e0; e < E; e++) {
                int dd = dst[e];
                int pp = atomicAdd(&g_cnt[dd], 1);
                if (pp < CAP) g_eidx[(dd << CAP_SHIFT) + pp] = src[e];
            }
        }
        __syncthreads();
        if (threadIdx.x == 0) {
            __threadfence();                    // publish g_cnt/g_eidx
            atomicAdd(&g_done, 1);
        }
        return;
    }

    // ------------- gemm1 (FFMA2): 64 nodes per block -------------
    int tid = threadIdx.x;
    for (int t = tid; t < D_IN * D_HID; t += blockDim.x) sW[t] = W1[t];

    int row0 = (blockIdx.x - FILL_BLOCKS) * G1_TILE;
#pragma unroll
    for (int it = 0; it < 8; it++) {
        int pos = tid + it * 256;
        int r = pos >> 5, c4 = pos & 31;
        if (row0 + r < N_NODES) {
            float4 v = ldcg4(x + (size_t)(row0 + r) * D_IN + c4 * 4);
            *(float4*)&sX[r * G1_XPAD + c4 * 4] = v;
        }
    }
    __syncthreads();

    int local = tid >> 2, q = tid & 3;
    int i = row0 + local;

    unsigned sW_base = (unsigned)__cvta_generic_to_shared(sW) + q * 16;
    unsigned long long a01 = 0ull, a23 = 0ull;
    if (i < N_NODES) {
#pragma unroll
        for (int j4 = 0; j4 < 32; j4++) {
            float4 v = *(const float4*)&sX[local * G1_XPAD + j4 * 4];
#pragma unroll
            for (int t = 0; t < 4; t++) {
                float vt = t == 0 ? v.x : t == 1 ? v.y : t == 2 ? v.z : v.w;
                unsigned long long w01, w23;
                lds_v2u64(sW_base + (j4 * 4 + t) * (D_HID * 4), w01, w23);
                unsigned long long vv = pack2(vt, vt);
                fma2(a01, vv, w01);
                fma2(a23, vv, w23);
            }
        }
    }

    // wait for all fill blocks, then scale by dinv and store
    if (tid == 0) {
        while (ld_acquire(&g_done) < FILL_BLOCKS) __nanosleep(64);
    }
    __syncthreads();

    if (i < N_NODES) {
        float di = rsqrtf((float)g_cnt[i] + 1.0f);
        float r0, r1, r2, r3;
        unpack2(a01, r0, r1);
        unpack2(a23, r2, r3);
        *(float4*)(g_h1s + (size_t)i * D_HID + q * 4) =
            make_float4(r0 * di, r1 * di, r2 * di, r3 * di);
    }
}

// ---------------------------------------------------------------------------
// Shared gather core: straight-line 3x-unrolled predicated gather (deg<=24,
// 97.7% of nodes) + rare warp-uniform tail.
__device__ __forceinline__ float4 gather_sum(const float* feat, int gw, int cnt,
                                             int base, int q, int s) {
    float4 acc = make_float4(0.f, 0.f, 0.f, 0.f);
#pragma unroll
    for (int it = 0; it < 3; it++) {
        int e = s + it * 8;
        int sn = ldcg1(&g_eidx[base + e]);
        sn = (e < cnt) ? sn : gw;
        float4 f = ldcg4(feat + (size_t)sn * D_HID + q * 4);
        if (e < cnt) {
            acc.x += f.x; acc.y += f.y; acc.z += f.z; acc.w += f.w;
        }
    }
    if (cnt > 24) {                         // warp-uniform rare tail
        for (int e = 24 + s; e < cnt; e += 8) {
            int sn = ldcg1(&g_eidx[base + e]);
            float4 f = ldcg4(feat + (size_t)sn * D_HID + q * 4);
            acc.x += f.x; acc.y += f.y; acc.z += f.z; acc.w += f.w;
        }
    }
    if (s == 0) {                           // self loop
        float4 f = ldcg4(feat + (size_t)gw * D_HID + q * 4);
        acc.x += f.x; acc.y += f.y; acc.z += f.z; acc.w += f.w;
    }
#pragma unroll
    for (int m = 4; m < 32; m <<= 1) {
        acc.x += __shfl_xor_sync(0xffffffffu, acc.x, m);
        acc.y += __shfl_xor_sync(0xffffffffu, acc.y, m);
        acc.z += __shfl_xor_sync(0xffffffffu, acc.z, m);
        acc.w += __shfl_xor_sync(0xffffffffu, acc.w, m);
    }
    return acc;
}

// ---------------------------------------------------------------------------
// gather pass 1: zs_i = (dinv_i * (Σ h1s[src] + h1s[i]) + b1) * dinv_i
__global__ void k_gather1(const float* __restrict__ b1) {
    int gw = (blockIdx.x * blockDim.x + threadIdx.x) >> 5;
    if (gw >= N_NODES) return;
    int lane = threadIdx.x & 31;
    int q = lane & 3, s = lane >> 2;

    int cntRaw = g_cnt[gw];
    int cnt = min(cntRaw, CAP);
    float4 acc = gather_sum(g_h1s, gw, cnt, gw << CAP_SHIFT, q, s);

    if (lane < 4) {
        float di = rsqrtf((float)cntRaw + 1.0f);
        float4 b = ((const float4*)b1)[q];
        float4 z;
        z.x = (di * acc.x + b.x) * di;
        z.y = (di * acc.y + b.y) * di;
        z.z = (di * acc.z + b.z) * di;
        z.w = (di * acc.w + b.w) * di;
        *(float4*)(g_zs + (size_t)gw * D_HID + q * 4) = z;
    }
}

// ---------------------------------------------------------------------------
// gather pass 2 + decoder GEMM. 256 threads, 8 nodes/block.
// No W2 smem staging: Phase B reads W2 directly (L1-resident, broadcast).
#define SV_STRIDE 36
__global__ void k_gather2out(const float* __restrict__ W2, const float* __restrict__ b2,
                             float* __restrict__ out) {
    __shared__ __align__(16) float sv[8 * SV_STRIDE];

    int w = threadIdx.x >> 5;
    int lane = threadIdx.x & 31;
    int gw = blockIdx.x * 8 + w;                 // 6250*8 == 50000 exactly

    if (blockIdx.x == 0 && threadIdx.x == 0) g_done = 0;  // reset handshake for next replay

    // ---- Phase A: gather & reduce for node gw ----
    {
        int q = lane & 3, s = lane >> 2;
        int cntRaw = g_cnt[gw];
        int cnt = min(cntRaw, CAP);
        float4 acc = gather_sum(g_zs, gw, cnt, gw << CAP_SHIFT, q, s);
        if (lane < 4) {
            float di = rsqrtf((float)cntRaw + 1.0f);
            *(float4*)&sv[w * SV_STRIDE + q * 4] =
                make_float4(di * acc.x, di * acc.y, di * acc.z, di * acc.w);
        }
        if (lane == 0) g_cnt[gw] = 0;           // self-clean for next replay
    }
    __syncthreads();

    // ---- Phase B (FFMA2, W2 direct from global): warp w -> cols [16w,16w+16) ----
    int n  = lane >> 2;
    int c4 = lane & 3;
    int col = w * 16 + c4 * 4;

    float4 vv[4];
#pragma unroll
    for (int kk = 0; kk < 4; kk++)
        vv[kk] = *(const float4*)&sv[n * SV_STRIDE + kk * 4];

    float4 b = __ldg((const float4*)(b2 + col));
    unsigned long long a01 = pack2(b.x, b.y);
    unsigned long long a23 = pack2(b.z, b.w);
    const float* wp = W2 + col;
#pragma unroll
    for (int k = 0; k < D_HID; k++) {
        float vk = (k & 3) == 0 ? vv[k >> 2].x : (k & 3) == 1 ? vv[k >> 2].y
                 : (k & 3) == 2 ? vv[k >> 2].z : vv[k >> 2].w;
        unsigned long long w01, w23;
        ldg_v2u64(wp + k * D_IN, w01, w23);
        unsigned long long vp = pack2(vk, vk);
        fma2(a01, vp, w01);
        fma2(a23, vp, w23);
    }
    float r0, r1, r2, r3;
    unpack2(a01, r0, r1);
    unpack2(a23, r2, r3);
    *(float4*)(out + (size_t)(blockIdx.x * 8 + n) * D_IN + col) =
        make_float4(r0, r1, r2, r3);
}

// ---------------------------------------------------------------------------
extern "C" void kernel_launch(void* const* d_in, const int* in_sizes, int n_in,
                              void* d_out, int out_size) {
    const float* x  = (const float*)d_in[0];
    const int*   ei = (const int*)  d_in[1];
    const float* W1 = (const float*)d_in[2];
    const float* b1 = (const float*)d_in[3];
    const float* W2 = (const float*)d_in[4];
    const float* b2 = (const float*)d_in[5];
    float* out = (float*)d_out;

    int E = in_sizes[1] / 2;
    const int* src = ei;
    const int* dst = ei + E;

    const int T = 256;
    int gemmBlocks = (N_NODES + G1_TILE - 1) / G1_TILE;
    k_fill_gemm1<<<FILL_BLOCKS + gemmBlocks, T>>>(src, dst, E, x, W1);
    k_gather1   <<<(N_NODES * 32 + T - 1) / T, T>>>(b1);
    k_gather2out<<<N_NODES / 8, T>>>(W2, b2, out);
}

// round 13
// speedup vs baseline: 1.0496x; 1.0496x over previous
#include <cuda_runtime.h>
#include <cuda_fp16.h>
#include <cuda_bf16.h>

#define N_NODES  50000
#define D_IN     128
#define D_HID    16
#define E_MAX    800000
#define CAP      128            // bucket capacity per node (Poisson(16): overflow prob ~0)
#define CAP_SHIFT 7

// ---- scratch (__device__ globals; zero-initialized at load; self-cleaning) ----
__device__ int g_cnt[N_NODES];                    // degree; reset by k_gather2out
__device__ int g_eidx[N_NODES * CAP];             // src buckets, one fixed region per dst
__device__ __align__(16) __half g_h1s[N_NODES * D_HID];  // (x@W1)*dinv_i, fp16 rows (32B)
__device__ __align__(16) __half g_zs [N_NODES * D_HID];  // z*dinv_i, fp16 rows (32B)

__device__ __forceinline__ float4 ldcg4(const float* p) {
    float4 v;
    asm volatile("ld.global.cg.v4.f32 {%0,%1,%2,%3}, [%4];"
                 : "=f"(v.x), "=f"(v.y), "=f"(v.z), "=f"(v.w) : "l"(p));
    return v;
}
__device__ __forceinline__ int ldcg1(const int* p) {
    int v;
    asm volatile("ld.global.cg.s32 %0, [%1];" : "=r"(v) : "l"(p));
    return v;
}
// 8B fp16x4 gather load (bypass L1) -> fp32x4
__device__ __forceinline__ float4 ldcg_h4(const __half* p) {
    unsigned a, b;
    asm volatile("ld.global.cg.v2.u32 {%0,%1}, [%2];" : "=r"(a), "=r"(b) : "l"(p));
    __half2 h0 = *reinterpret_cast<__half2*>(&a);
    __half2 h1 = *reinterpret_cast<__half2*>(&b);
    float2 f0 = __half22float2(h0), f1 = __half22float2(h1);
    return make_float4(f0.x, f0.y, f1.x, f1.y);
}
// store 4 fp32 -> 4 fp16 (8B)
__device__ __forceinline__ void st_h4(__half* p, float a, float b, float c, float d) {
    __half2 h0 = __floats2half2_rn(a, b);
    __half2 h1 = __floats2half2_rn(c, d);
    uint2 u;
    u.x = *reinterpret_cast<unsigned*>(&h0);
    u.y = *reinterpret_cast<unsigned*>(&h1);
    *reinterpret_cast<uint2*>(p) = u;
}

// ---- packed f32x2 (Blackwell FFMA2) ----
__device__ __forceinline__ unsigned long long pack2(float lo, float hi) {
    unsigned long long r;
    asm("mov.b64 %0, {%1, %2};" : "=l"(r) : "f"(lo), "f"(hi));
    return r;
}
__device__ __forceinline__ void unpack2(unsigned long long p, float& lo, float& hi) {
    asm("mov.b64 {%0, %1}, %2;" : "=f"(lo), "=f"(hi) : "l"(p));
}
__device__ __forceinline__ void fma2(unsigned long long& acc, unsigned long long a,
                                     unsigned long long b) {
    asm("fma.rn.f32x2 %0, %1, %2, %0;" : "+l"(acc) : "l"(a), "l"(b));
}
__device__ __forceinline__ void lds_v2u64(unsigned addr, unsigned long long& w01,
                                          unsigned long long& w23) {
    asm("ld.shared.v2.u64 {%0, %1}, [%2];" : "=l"(w01), "=l"(w23) : "r"(addr));
}
__device__ __forceinline__ void ldg_v2u64(const float* p, unsigned long long& w01,
                                          unsigned long long& w23) {
    asm("ld.global.nc.v2.u64 {%0, %1}, [%2];" : "=l"(w01), "=l"(w23) : "l"(p));
}

#define G1_TILE 64
#define G1_XPAD 132
#define FILL_BLOCKS ((E_MAX / 16 + 255) / 256)    // 196 for E=800000

// ---------------------------------------------------------------------------
// Fat kernel: blocks [0,FILL_BLOCKS) build CSR buckets; remaining blocks
// compute h1 = x @ W1 UNSCALED (fp16 store) — phases overlap, no handshake.
__global__ void k_fill_gemm1(const int* __restrict__ src, const int* __restrict__ dst,
                             int E, const float* __restrict__ x,
                             const float* __restrict__ W1) {
    __shared__ __align__(16) float sW[D_IN * D_HID];       // 8 KB
    __shared__ __align__(16) float sX[G1_TILE * G1_XPAD];  // ~33 KB

    if (blockIdx.x < FILL_BLOCKS) {
        int t = blockIdx.x * blockDim.x + threadIdx.x;
        int e0 = t * 16;
        if (e0 + 15 < E) {
            int4 d[4], s[4];
#pragma unroll
            for (int c = 0; c < 4; c++) {
                d[c] = *(const int4*)(dst + e0 + c * 4);
                s[c] = *(const int4*)(src + e0 + c * 4);
            }
            int p[16];
#pragma unroll
            for (int c = 0; c < 4; c++) {
                p[c * 4 + 0] = atomicAdd(&g_cnt[d[c].x], 1);
                p[c * 4 + 1] = atomicAdd(&g_cnt[d[c].y], 1);
                p[c * 4 + 2] = atomicAdd(&g_cnt[d[c].z], 1);
                p[c * 4 + 3] = atomicAdd(&g_cnt[d[c].w], 1);
            }
#pragma unroll
            for (int c = 0; c < 4; c++) {
                if (p[c*4+0] < CAP) g_eidx[(d[c].x << CAP_SHIFT) + p[c*4+0]] = s[c].x;
                if (p[c*4+1] < CAP) g_eidx[(d[c].y << CAP_SHIFT) + p[c*4+1]] = s[c].y;
                if (p[c*4+2] < CAP) g_eidx[(d[c].z << CAP_SHIFT) + p[c*4+2]] = s[c].z;
                if (p[c*4+3] < CAP) g_eidx[(d[c].w << CAP_SHIFT) + p[c*4+3]] = s[c].w;
            }
        } else {
            for (int e = e0; e < E; e++) {
                int dd = dst[e];
                int pp = atomicAdd(&g_cnt[dd], 1);
                if (pp < CAP) g_eidx[(dd << CAP_SHIFT) + pp] = src[e];
            }
        }
        return;
    }

    // ------------- gemm1 (unscaled, FFMA2): 64 nodes per block -------------
    int tid = threadIdx.x;
    for (int t = tid; t < D_IN * D_HID; t += blockDim.x) sW[t] = W1[t];

    int row0 = (blockIdx.x - FILL_BLOCKS) * G1_TILE;
#pragma unroll
    for (int it = 0; it < 8; it++) {
        int pos = tid + it * 256;
        int r = pos >> 5, c4 = pos & 31;
        if (row0 + r < N_NODES) {
            float4 v = ldcg4(x + (size_t)(row0 + r) * D_IN + c4 * 4);
            *(float4*)&sX[r * G1_XPAD + c4 * 4] = v;
        }
    }
    __syncthreads();

    int local = tid >> 2, q = tid & 3;
    int i = row0 + local;
    if (i >= N_NODES) return;

    unsigned sW_base = (unsigned)__cvta_generic_to_shared(sW) + q * 16;
    unsigned long long a01 = 0ull, a23 = 0ull;
#pragma unroll
    for (int j4 = 0; j4 < 32; j4++) {
        float4 v = *(const float4*)&sX[local * G1_XPAD + j4 * 4];
#pragma unroll
        for (int t = 0; t < 4; t++) {
            float vt = t == 0 ? v.x : t == 1 ? v.y : t == 2 ? v.z : v.w;
            unsigned long long w01, w23;
            lds_v2u64(sW_base + (j4 * 4 + t) * (D_HID * 4), w01, w23);
            unsigned long long vv = pack2(vt, vt);
            fma2(a01, vv, w01);
            fma2(a23, vv, w23);
        }
    }
    float r0, r1, r2, r3;
    unpack2(a01, r0, r1);
    unpack2(a23, r2, r3);
    st_h4(g_h1s + (size_t)i * D_HID + q * 4, r0, r1, r2, r3);   // unscaled
}

// ---------------------------------------------------------------------------
// h1s *= dinv_i  (after fill+gemm1 join; thread per 4 halves)
__global__ void k_scale() {
    int t = blockIdx.x * blockDim.x + threadIdx.x;
    int i = t >> 2, q = t & 3;
    if (i >= N_NODES) return;
    float di = rsqrtf((float)g_cnt[i] + 1.0f);
    __half* p = g_h1s + (size_t)i * D_HID + q * 4;
    float4 v = ldcg_h4(p);
    st_h4(p, v.x * di, v.y * di, v.z * di, v.w * di);
}

// ---------------------------------------------------------------------------
// Shared gather core over fp16 rows: straight-line 3x-unrolled predicated
// gather (deg<=24, 97.7% of nodes) + rare warp-uniform tail.
__device__ __forceinline__ float4 gather_sum(const __half* feat, int gw, int cnt,
                                             int base, int q, int s) {
    float4 acc = make_float4(0.f, 0.f, 0.f, 0.f);
#pragma unroll
    for (int it = 0; it < 3; it++) {
        int e = s + it * 8;
        int sn = ldcg1(&g_eidx[base + e]);
        sn = (e < cnt) ? sn : gw;
        float4 f = ldcg_h4(feat + (size_t)sn * D_HID + q * 4);
        if (e < cnt) {
            acc.x += f.x; acc.y += f.y; acc.z += f.z; acc.w += f.w;
        }
    }
    if (cnt > 24) {
        for (int e = 24 + s; e < cnt; e += 8) {
            int sn = ldcg1(&g_eidx[base + e]);
            float4 f = ldcg_h4(feat + (size_t)sn * D_HID + q * 4);
            acc.x += f.x; acc.y += f.y; acc.z += f.z; acc.w += f.w;
        }
    }
    if (s == 0) {                           // self loop
        float4 f = ldcg_h4(feat + (size_t)gw * D_HID + q * 4);
        acc.x += f.x; acc.y += f.y; acc.z += f.z; acc.w += f.w;
    }
#pragma unroll
    for (int m = 4; m < 32; m <<= 1) {
        acc.x += __shfl_xor_sync(0xffffffffu, acc.x, m);
        acc.y += __shfl_xor_sync(0xffffffffu, acc.y, m);
        acc.z += __shfl_xor_sync(0xffffffffu, acc.z, m);
        acc.w += __shfl_xor_sync(0xffffffffu, acc.w, m);
    }
    return acc;
}

// ---------------------------------------------------------------------------
// gather pass 1: zs_i = (dinv_i * (Σ h1s[src] + h1s[i]) + b1) * dinv_i
__global__ void k_gather1(const float* __restrict__ b1) {
    int gw = (blockIdx.x * blockDim.x + threadIdx.x) >> 5;
    if (gw >= N_NODES) return;
    int lane = threadIdx.x & 31;
    int q = lane & 3, s = lane >> 2;

    int cntRaw = g_cnt[gw];
    int cnt = min(cntRaw, CAP);
    float4 acc = gather_sum(g_h1s, gw, cnt, gw << CAP_SHIFT, q, s);

    if (lane < 4) {
        float di = rsqrtf((float)cntRaw + 1.0f);
        float4 b = ((const float4*)b1)[q];
        st_h4(g_zs + (size_t)gw * D_HID + q * 4,
              (di * acc.x + b.x) * di, (di * acc.y + b.y) * di,
              (di * acc.z + b.z) * di, (di * acc.w + b.w) * di);
    }
}

// ---------------------------------------------------------------------------
// gather pass 2 + decoder GEMM. 256 threads, 8 nodes/block.
// W2 read directly from global (L1-resident, broadcast) with FFMA2.
#define SV_STRIDE 36
__global__ void k_gather2out(const float* __restrict__ W2, const float* __restrict__ b2,
                             float* __restrict__ out) {
    __shared__ __align__(16) float sv[8 * SV_STRIDE];

    int w = threadIdx.x >> 5;
    int lane = threadIdx.x & 31;
    int gw = blockIdx.x * 8 + w;                 // 6250*8 == 50000 exactly

    // ---- Phase A: gather & reduce for node gw ----
    {
        int q = lane & 3, s = lane >> 2;
        int cntRaw = g_cnt[gw];
        int cnt = min(cntRaw, CAP);
        float4 acc = gather_sum(g_zs, gw, cnt, gw << CAP_SHIFT, q, s);
        if (lane < 4) {
            float di = rsqrtf((float)cntRaw + 1.0f);
            *(float4*)&sv[w * SV_STRIDE + q * 4] =
                make_float4(di * acc.x, di * acc.y, di * acc.z, di * acc.w);
        }
        if (lane == 0) g_cnt[gw] = 0;           // self-clean for next replay
    }
    __syncthreads();

    // ---- Phase B (FFMA2, W2 direct): warp w -> cols [16w,16w+16) of 8 nodes ----
    int n  = lane >> 2;
    int c4 = lane & 3;
    int col = w * 16 + c4 * 4;

    float4 vv[4];
#pragma unroll
    for (int kk = 0; kk < 4; kk++)
        vv[kk] = *(const float4*)&sv[n * SV_STRIDE + kk * 4];

    float4 b = __ldg((const float4*)(b2 + col));
    unsigned long long a01 = pack2(b.x, b.y);
    unsigned long long a23 = pack2(b.z, b.w);
    const float* wp = W2 + col;
#pragma unroll
    for (int k = 0; k < D_HID; k++) {
        float vk = (k & 3) == 0 ? vv[k >> 2].x : (k & 3) == 1 ? vv[k >> 2].y
                 : (k & 3) == 2 ? vv[k >> 2].z : vv[k >> 2].w;
        unsigned long long w01, w23;
        ldg_v2u64(wp + k * D_IN, w01, w23);
        unsigned long long vp = pack2(vk, vk);
        fma2(a01, vp, w01);
        fma2(a23, vp, w23);
    }
    float r0, r1, r2, r3;
    unpack2(a01, r0, r1);
    unpack2(a23, r2, r3);
    *(float4*)(out + (size_t)(blockIdx.x * 8 + n) * D_IN + col) =
        make_float4(r0, r1, r2, r3);
}

// ---------------------------------------------------------------------------
extern "C" void kernel_launch(void* const* d_in, const int* in_sizes, int n_in,
                              void* d_out, int out_size) {
    const float* x  = (const float*)d_in[0];
    const int*   ei = (const int*)  d_in[1];
    const float* W1 = (const float*)d_in[2];
    const float* b1 = (const float*)d_in[3];
    const float* W2 = (const float*)d_in[4];
    const float* b2 = (const float*)d_in[5];
    float* out = (float*)d_out;

    int E = in_sizes[1] / 2;
    const int* src = ei;
    const int* dst = ei + E;

    const int T = 256;
    int gemmBlocks = (N_NODES + G1_TILE - 1) / G1_TILE;
    k_fill_gemm1<<<FILL_BLOCKS + gemmBlocks, T>>>(src, dst, E, x, W1);
    k_scale     <<<(N_NODES * 4 + T - 1) / T, T>>>();
    k_gather1   <<<(N_NODES * 32 + T - 1) / T, T>>>(b1);
    k_gather2out<<<N_NODES / 8, T>>>(W2, b2, out);
}